// round 5
// baseline (speedup 1.0000x reference)
#include <cuda_runtime.h>

typedef unsigned long long ull;

// out = (w1+w2)*s + (w3-w2)*G3(s) + (w4-w3)*G5(s) - w4*G7(s)
// Separable Gaussians. Scalar horizontal (FFMA-imm) on 4 cols/thread via 3x LDS.128,
// transposed-FIR vertical in packed f32x2 (7-slot ring). Tile 128x128, RPT=16, 3 CTAs/SM.

#define IMG 512
#define TX 128
#define TY 128
#define NTH 256
#define SW 136            // TX + 8 (left halo 4 for f4 alignment, right halo 4)
#define SH 134            // TY + 6
#define NF4 (SW / 4)      // 34
#define STEPS 22          // 16 output rows + 6 halo rows per row-group

#define K3_0 0.5220116f
#define K3_1 0.2389942f
#define K5_0 0.3695467f
#define K5_1 0.2444604f
#define K5_2 0.0707663f
#define K7_0 0.2880262f
#define K7_1 0.2231734f
#define K7_2 0.1038183f
#define K7_3 0.0289952f

__device__ __forceinline__ ull pk2(float lo, float hi) {
    ull r; asm("mov.b64 %0, {%1, %2};" : "=l"(r) : "f"(lo), "f"(hi)); return r;
}
__device__ __forceinline__ ull mul2(ull a, ull b) {
    ull r; asm("mul.rn.f32x2 %0, %1, %2;" : "=l"(r) : "l"(a), "l"(b)); return r;
}
__device__ __forceinline__ ull fma2(ull a, ull b, ull c) {
    ull r; asm("fma.rn.f32x2 %0, %1, %2, %3;" : "=l"(r) : "l"(a), "l"(b), "l"(c)); return r;
}

__global__ void __launch_bounds__(NTH, 3)
mgdf_kernel(const float* __restrict__ s,
            const float* __restrict__ w1p, const float* __restrict__ w2p,
            const float* __restrict__ w3p, const float* __restrict__ w4p,
            float* __restrict__ out)
{
    __shared__ __align__(16) float tile[SH][SW];

    const int img = blockIdx.z;
    const size_t base = (size_t)img * (IMG * IMG);
    const float* sp = s + base;
    float* op = out + base;

    const int tileX = blockIdx.x * TX;
    const int tileY = blockIdx.y * TY;
    const int tid = threadIdx.x;

    // ---- Stage 1: aligned float4 tile load, zero-padded; fast path for interior ----
    const bool interior = (tileY >= 3) && (tileY + (SH - 3) <= IMG) &&
                          (tileX >= 4) && (tileX + (SW - 4) <= IMG);
    if (interior) {
        #pragma unroll
        for (int idx = tid; idx < SH * NF4; idx += NTH) {
            int r = idx / NF4;
            int c4 = idx - r * NF4;
            *reinterpret_cast<float4*>(&tile[r][c4 * 4]) =
                *reinterpret_cast<const float4*>(sp + (tileY - 3 + r) * IMG + tileX - 4 + c4 * 4);
        }
    } else {
        #pragma unroll
        for (int idx = tid; idx < SH * NF4; idx += NTH) {
            int r = idx / NF4;
            int c4 = idx - r * NF4;
            int gy = tileY - 3 + r;
            int gx = tileX - 4 + c4 * 4;
            float4 v = make_float4(0.f, 0.f, 0.f, 0.f);
            if ((unsigned)gy < (unsigned)IMG && (unsigned)gx < (unsigned)IMG)
                v = *reinterpret_cast<const float4*>(sp + gy * IMG + gx);
            *reinterpret_cast<float4*>(&tile[r][c4 * 4]) = v;
        }
    }
    __syncthreads();

    // ---- Runtime weights folded into vertical coefficients ----
    const float W1 = *w1p, W2 = *w2p, W3 = *w3p, W4 = *w4p;
    const float cA = W1 + W2;
    const float cB = W3 - W2;
    const float cC = W4 - W3;
    const float cD = -W4;
    const ull cAp = pk2(cA, cA);
    const ull a30 = pk2(cB * K3_0, cB * K3_0);
    const ull a31 = pk2(cB * K3_1, cB * K3_1);
    const ull a50 = pk2(cC * K5_0, cC * K5_0);
    const ull a51 = pk2(cC * K5_1, cC * K5_1);
    const ull a52 = pk2(cC * K5_2, cC * K5_2);
    const ull a70 = pk2(cD * K7_0, cD * K7_0);
    const ull a71 = pk2(cD * K7_1, cD * K7_1);
    const ull a72 = pk2(cD * K7_2, cD * K7_2);
    const ull a73 = pk2(cD * K7_3, cD * K7_3);

    const int xg = tid & 31;            // 32 column groups of 4 cols -> 128 cols
    const int rg = tid >> 5;            // 8 row groups of 16 rows
    const int cb = 4 * xg;              // smem col of first float4 (centers at cb+4..cb+7)
    const int rowBase = rg * 16;
    float* orow = op + (size_t)(tileY + rowBase) * IMG + tileX + 4 * xg;

    // 7-slot accumulator ring, 2 ull lanes (4 cols); indices compile-time under unroll
    ull acc[7][2];

    #pragma unroll
    for (int k = 0; k < STEPS; k++) {
        const int sr = rowBase + k;

        // ---- horizontal pass: 3x LDS.128 cover all 10 taps for 4 cols ----
        float4 A = *reinterpret_cast<const float4*>(&tile[sr][cb]);
        float4 B = *reinterpret_cast<const float4*>(&tile[sr][cb + 4]);
        float4 C = *reinterpret_cast<const float4*>(&tile[sr][cb + 8]);
        float x0 = A.x, x1 = A.y, x2 = A.z, x3 = A.w;
        float x4 = B.x, x5 = B.y, x6 = B.z, x7 = B.w;
        float x8 = C.x, x9 = C.y, x10 = C.z;

        float h3v[4], h5v[4], h7v[4];
        {
            float p1, p2, p3;
            p1 = x3 + x5;  p2 = x2 + x6;  p3 = x1 + x7;
            h3v[0] = K3_0 * x4 + K3_1 * p1;
            h5v[0] = K5_0 * x4 + K5_1 * p1 + K5_2 * p2;
            h7v[0] = K7_0 * x4 + K7_1 * p1 + K7_2 * p2 + K7_3 * p3;
            p1 = x4 + x6;  p2 = x3 + x7;  p3 = x2 + x8;
            h3v[1] = K3_0 * x5 + K3_1 * p1;
            h5v[1] = K5_0 * x5 + K5_1 * p1 + K5_2 * p2;
            h7v[1] = K7_0 * x5 + K7_1 * p1 + K7_2 * p2 + K7_3 * p3;
            p1 = x5 + x7;  p2 = x4 + x8;  p3 = x3 + x9;
            h3v[2] = K3_0 * x6 + K3_1 * p1;
            h5v[2] = K5_0 * x6 + K5_1 * p1 + K5_2 * p2;
            h7v[2] = K7_0 * x6 + K7_1 * p1 + K7_2 * p2 + K7_3 * p3;
            p1 = x6 + x8;  p2 = x5 + x9;  p3 = x4 + x10;
            h3v[3] = K3_0 * x7 + K3_1 * p1;
            h5v[3] = K5_0 * x7 + K5_1 * p1 + K5_2 * p2;
            h7v[3] = K7_0 * x7 + K7_1 * p1 + K7_2 * p2 + K7_3 * p3;
        }
        ull t3a = pk2(h3v[0], h3v[1]), t3b = pk2(h3v[2], h3v[3]);
        ull t5a = pk2(h5v[0], h5v[1]), t5b = pk2(h5v[2], h5v[3]);
        ull t7a = pk2(h7v[0], h7v[1]), t7b = pk2(h7v[2], h7v[3]);
        ull rwa = pk2(x4, x5),          rwb = pk2(x6, x7);

        // ---- transposed vertical: scatter row k into in-flight outputs ----
        if (k <= 15) {                                   // d=0 (init slot)
            acc[k % 7][0] = mul2(a73, t7a);
            acc[k % 7][1] = mul2(a73, t7b);
        }
        if (k >= 1 && k <= 16) {                         // d=1
            ull u = acc[(k - 1) % 7][0], v = acc[(k - 1) % 7][1];
            u = fma2(a72, t7a, u);  v = fma2(a72, t7b, v);
            u = fma2(a52, t5a, u);  v = fma2(a52, t5b, v);
            acc[(k - 1) % 7][0] = u; acc[(k - 1) % 7][1] = v;
        }
        if (k >= 2 && k <= 17) {                         // d=2
            ull u = acc[(k - 2) % 7][0], v = acc[(k - 2) % 7][1];
            u = fma2(a71, t7a, u);  v = fma2(a71, t7b, v);
            u = fma2(a51, t5a, u);  v = fma2(a51, t5b, v);
            u = fma2(a31, t3a, u);  v = fma2(a31, t3b, v);
            acc[(k - 2) % 7][0] = u; acc[(k - 2) % 7][1] = v;
        }
        if (k >= 3 && k <= 18) {                         // d=3 (center)
            ull u = acc[(k - 3) % 7][0], v = acc[(k - 3) % 7][1];
            u = fma2(a70, t7a, u);  v = fma2(a70, t7b, v);
            u = fma2(a50, t5a, u);  v = fma2(a50, t5b, v);
            u = fma2(a30, t3a, u);  v = fma2(a30, t3b, v);
            u = fma2(cAp, rwa, u);  v = fma2(cAp, rwb, v);
            acc[(k - 3) % 7][0] = u; acc[(k - 3) % 7][1] = v;
        }
        if (k >= 4 && k <= 19) {                         // d=4
            ull u = acc[(k - 4) % 7][0], v = acc[(k - 4) % 7][1];
            u = fma2(a71, t7a, u);  v = fma2(a71, t7b, v);
            u = fma2(a51, t5a, u);  v = fma2(a51, t5b, v);
            u = fma2(a31, t3a, u);  v = fma2(a31, t3b, v);
            acc[(k - 4) % 7][0] = u; acc[(k - 4) % 7][1] = v;
        }
        if (k >= 5 && k <= 20) {                         // d=5
            ull u = acc[(k - 5) % 7][0], v = acc[(k - 5) % 7][1];
            u = fma2(a72, t7a, u);  v = fma2(a72, t7b, v);
            u = fma2(a52, t5a, u);  v = fma2(a52, t5b, v);
            acc[(k - 5) % 7][0] = u; acc[(k - 5) % 7][1] = v;
        }
        if (k >= 6) {                                    // d=6: finish + STG.128
            ulonglong2 o;
            o.x = fma2(a73, t7a, acc[(k - 6) % 7][0]);
            o.y = fma2(a73, t7b, acc[(k - 6) % 7][1]);
            *reinterpret_cast<ulonglong2*>(orow + (size_t)(k - 6) * IMG) = o;
        }
    }
}

extern "C" void kernel_launch(void* const* d_in, const int* in_sizes, int n_in,
                              void* d_out, int out_size)
{
    const float* s  = (const float*)d_in[0];
    const float* w1 = (const float*)d_in[1];
    const float* w2 = (const float*)d_in[2];
    const float* w3 = (const float*)d_in[3];
    const float* w4 = (const float*)d_in[4];
    float* out = (float*)d_out;

    const int n_img = in_sizes[0] / (IMG * IMG);       // 192
    dim3 grid(IMG / TX, IMG / TY, n_img);              // (4, 4, 192)
    mgdf_kernel<<<grid, NTH>>>(s, w1, w2, w3, w4, out);
}